// round 5
// baseline (speedup 1.0000x reference)
#include <cuda_runtime.h>

#define VQ_D 64
#define BLOCK_THREADS 256
#define MAX_BLOCKS 8192

typedef unsigned long long u64;

// Per-block partial sums of sum((quantized - x)^2); fixed-order reduced by kernel 2.
__device__ float g_vq_partials[MAX_BLOCKS];

// ---- packed f32x2 helpers (FFMA2 is only reachable via hand-written PTX) ----
__device__ __forceinline__ u64 fma2(u64 a, u64 b, u64 c) {
    u64 d;
    asm("fma.rn.f32x2 %0, %1, %2, %3;" : "=l"(d) : "l"(a), "l"(b), "l"(c));
    return d;
}
__device__ __forceinline__ u64 add2(u64 a, u64 b) {
    u64 d;
    asm("add.rn.f32x2 %0, %1, %2;" : "=l"(d) : "l"(a), "l"(b));
    return d;
}
__device__ __forceinline__ float2 u2f(u64 a) {
    float2 r;
    r.x = __uint_as_float((unsigned int)(a & 0xffffffffull));
    r.y = __uint_as_float((unsigned int)(a >> 32));
    return r;
}

// ---------------------------------------------------------------------------
// Main kernel: one thread = one x row. Codebook + per-code norms live in smem.
// dist_k = (||x||^2 + ||e_k||^2) - 2 * <x, e_k>   (matches reference rounding:
// the xx+ee add happens first, the 2*dot multiply and subtract are NOT fused).
// Argmin tie-break: strict '<' keeps the lowest index, matching jnp.argmin.
// ---------------------------------------------------------------------------
__global__ void __launch_bounds__(BLOCK_THREADS, 1)
vq_main_kernel(const float* __restrict__ x,
               const float* __restrict__ cb,
               float* __restrict__ out,
               int n, int K)
{
    extern __shared__ float sh[];
    float* sh_cb  = sh;                         // K * 64 floats
    float* sh_ee  = sh + (size_t)K * VQ_D;      // K floats
    float* sh_red = sh_ee + K;                  // 32 floats (block reduce)

    const int tid = threadIdx.x;

    // --- load codebook into shared (coalesced float4) ---
    {
        const float4* cb4 = (const float4*)cb;
        float4* sh4 = (float4*)sh_cb;
        const int total4 = K * VQ_D / 4;
        for (int i = tid; i < total4; i += BLOCK_THREADS) sh4[i] = cb4[i];
    }
    __syncthreads();

    // --- per-code squared norms (4 chains, near-pairwise accuracy) ---
    for (int kk = tid; kk < K; kk += BLOCK_THREADS) {
        const float* e = sh_cb + (size_t)kk * VQ_D;
        float a0 = 0.f, a1 = 0.f, a2 = 0.f, a3 = 0.f;
        #pragma unroll
        for (int j = 0; j < VQ_D; j += 4) {
            a0 = fmaf(e[j+0], e[j+0], a0);
            a1 = fmaf(e[j+1], e[j+1], a1);
            a2 = fmaf(e[j+2], e[j+2], a2);
            a3 = fmaf(e[j+3], e[j+3], a3);
        }
        sh_ee[kk] = __fadd_rn(__fadd_rn(a0, a1), __fadd_rn(a2, a3));
    }
    __syncthreads();

    const int row = blockIdx.x * BLOCK_THREADS + tid;
    float s_loss = 0.f;

    if (row < n) {
        // --- x row into registers as 32 packed f32x2 values ---
        u64 xr[VQ_D / 2];
        {
            const ulonglong2* xp = (const ulonglong2*)(x + (size_t)row * VQ_D);
            #pragma unroll
            for (int j = 0; j < VQ_D / 4; j++) {
                ulonglong2 v = xp[j];
                xr[2*j]   = v.x;
                xr[2*j+1] = v.y;
            }
        }

        // --- ||x||^2 ---
        float xx;
        {
            float a0 = 0.f, a1 = 0.f, a2 = 0.f, a3 = 0.f;
            #pragma unroll
            for (int j = 0; j < VQ_D / 2; j += 2) {
                float2 fa = u2f(xr[j]), fb = u2f(xr[j+1]);
                a0 = fmaf(fa.x, fa.x, a0);
                a1 = fmaf(fa.y, fa.y, a1);
                a2 = fmaf(fb.x, fb.x, a2);
                a3 = fmaf(fb.y, fb.y, a3);
            }
            xx = __fadd_rn(__fadd_rn(a0, a1), __fadd_rn(a2, a3));
        }

        // --- argmin over K codes ---
        float best = 3.402823466e38f;
        int   bi   = 0;
        const ulonglong2* ebase = (const ulonglong2*)sh_cb;

        #pragma unroll 2
        for (int kk = 0; kk < K; kk++) {
            const ulonglong2* e = ebase + (size_t)kk * (VQ_D / 4);
            u64 a0 = 0ull, a1 = 0ull, a2 = 0ull, a3 = 0ull;
            #pragma unroll
            for (int j = 0; j < VQ_D / 4; j += 2) {
                ulonglong2 e0 = e[j];
                ulonglong2 e1 = e[j + 1];
                a0 = fma2(e0.x, xr[2*j    ], a0);
                a1 = fma2(e0.y, xr[2*j + 1], a1);
                a2 = fma2(e1.x, xr[2*j + 2], a2);
                a3 = fma2(e1.y, xr[2*j + 3], a3);
            }
            u64 s = add2(add2(a0, a1), add2(a2, a3));
            float2 sf = u2f(s);
            float dot  = __fadd_rn(sf.x, sf.y);
            // (xx + ee) first, then subtract 2*dot WITHOUT fma contraction
            float dist = __fadd_rn(__fadd_rn(xx, sh_ee[kk]),
                                   -__fmul_rn(2.0f, dot));
            if (dist < best) { best = dist; bi = kk; }
        }

        // --- outputs: index (as float), quantized row, loss partial ---
        out[row] = (float)bi;

        const float*  e  = sh_cb + (size_t)bi * VQ_D;
        const float4* e4 = (const float4*)e;
        float4* q4 = (float4*)(out + (size_t)n + (size_t)row * VQ_D);
        #pragma unroll
        for (int j = 0; j < VQ_D / 4; j++) q4[j] = e4[j];

        float l0 = 0.f, l1 = 0.f, l2 = 0.f, l3 = 0.f;
        #pragma unroll
        for (int j2 = 0; j2 < VQ_D / 2; j2 += 2) {
            float2 fa = u2f(xr[j2]), fb = u2f(xr[j2 + 1]);
            float d0 = e[2*j2 + 0] - fa.x;
            float d1 = e[2*j2 + 1] - fa.y;
            float d2 = e[2*j2 + 2] - fb.x;
            float d3 = e[2*j2 + 3] - fb.y;
            l0 = fmaf(d0, d0, l0);
            l1 = fmaf(d1, d1, l1);
            l2 = fmaf(d2, d2, l2);
            l3 = fmaf(d3, d3, l3);
        }
        s_loss = __fadd_rn(__fadd_rn(l0, l1), __fadd_rn(l2, l3));
    }

    // --- deterministic block reduce of s_loss ---
    #pragma unroll
    for (int off = 16; off > 0; off >>= 1)
        s_loss += __shfl_down_sync(0xffffffffu, s_loss, off);
    if ((tid & 31) == 0) sh_red[tid >> 5] = s_loss;
    __syncthreads();
    if (tid == 0) {
        float t = 0.f;
        #pragma unroll
        for (int w = 0; w < BLOCK_THREADS / 32; w++) t += sh_red[w];
        g_vq_partials[blockIdx.x] = t;
    }
}

// ---------------------------------------------------------------------------
// Final deterministic reduction -> vq_loss = 1.25 * mean((q - x)^2)
// ---------------------------------------------------------------------------
__global__ void vq_reduce_kernel(float* __restrict__ out, int n, int nblocks)
{
    __shared__ double shd[BLOCK_THREADS];
    double s = 0.0;
    for (int i = threadIdx.x; i < nblocks; i += BLOCK_THREADS)
        s += (double)g_vq_partials[i];
    shd[threadIdx.x] = s;
    __syncthreads();
    for (int off = BLOCK_THREADS / 2; off > 0; off >>= 1) {
        if (threadIdx.x < off) shd[threadIdx.x] += shd[threadIdx.x + off];
        __syncthreads();
    }
    if (threadIdx.x == 0) {
        double mean = shd[0] / ((double)n * (double)VQ_D);
        out[(size_t)n + (size_t)n * VQ_D] = (float)(mean * 1.25);
    }
}

extern "C" void kernel_launch(void* const* d_in, const int* in_sizes, int n_in,
                              void* d_out, int out_size)
{
    const float* x  = (const float*)d_in[0];
    const float* cb = (const float*)d_in[1];
    float* out = (float*)d_out;

    const int n = in_sizes[0] / VQ_D;   // 524288
    const int K = in_sizes[1] / VQ_D;   // 512

    const int nblocks = (n + BLOCK_THREADS - 1) / BLOCK_THREADS;  // 2048
    const size_t smem = (size_t)K * VQ_D * sizeof(float)          // codebook
                      + (size_t)K * sizeof(float)                 // norms
                      + 64 * sizeof(float);                       // reduce pad

    cudaFuncSetAttribute(vq_main_kernel,
                         cudaFuncAttributeMaxDynamicSharedMemorySize,
                         (int)smem);

    vq_main_kernel<<<nblocks, BLOCK_THREADS, smem>>>(x, cb, out, n, K);
    vq_reduce_kernel<<<1, BLOCK_THREADS>>>(out, n, nblocks);
}

// round 6
// speedup vs baseline: 1.0021x; 1.0021x over previous
#include <cuda_runtime.h>

#define VQ_D 64
#define BLOCK_THREADS 256
#define MAX_BLOCKS 8192

typedef unsigned long long u64;

// Per-block partial sums of sum((quantized - x)^2); fixed-order reduced by kernel 2.
__device__ float g_vq_partials[MAX_BLOCKS];

// ---- packed f32x2 helpers (FFMA2 is only reachable via hand-written PTX) ----
__device__ __forceinline__ u64 fma2(u64 a, u64 b, u64 c) {
    u64 d;
    asm("fma.rn.f32x2 %0, %1, %2, %3;" : "=l"(d) : "l"(a), "l"(b), "l"(c));
    return d;
}
__device__ __forceinline__ u64 add2(u64 a, u64 b) {
    u64 d;
    asm("add.rn.f32x2 %0, %1, %2;" : "=l"(d) : "l"(a), "l"(b));
    return d;
}
__device__ __forceinline__ float2 u2f(u64 a) {
    float2 r;
    r.x = __uint_as_float((unsigned int)(a & 0xffffffffull));
    r.y = __uint_as_float((unsigned int)(a >> 32));
    return r;
}

// ---------------------------------------------------------------------------
// Main kernel: one thread = one x row. Codebook + per-code norms live in smem.
// dist_k = (||x||^2 + ||e_k||^2) - 2 * <x, e_k>   (matches reference rounding:
// the xx+ee add happens first, the 2*dot multiply and subtract are NOT fused).
// Argmin tie-break: strict '<' keeps the lowest index, matching jnp.argmin.
// ---------------------------------------------------------------------------
__global__ void __launch_bounds__(BLOCK_THREADS, 1)
vq_main_kernel(const float* __restrict__ x,
               const float* __restrict__ cb,
               float* __restrict__ out,
               int n, int K)
{
    extern __shared__ float sh[];
    float* sh_cb  = sh;                         // K * 64 floats
    float* sh_ee  = sh + (size_t)K * VQ_D;      // K floats
    float* sh_red = sh_ee + K;                  // 32 floats (block reduce)

    const int tid = threadIdx.x;

    // --- load codebook into shared (coalesced float4) ---
    {
        const float4* cb4 = (const float4*)cb;
        float4* sh4 = (float4*)sh_cb;
        const int total4 = K * VQ_D / 4;
        for (int i = tid; i < total4; i += BLOCK_THREADS) sh4[i] = cb4[i];
    }
    __syncthreads();

    // --- per-code squared norms (4 chains, near-pairwise accuracy) ---
    for (int kk = tid; kk < K; kk += BLOCK_THREADS) {
        const float* e = sh_cb + (size_t)kk * VQ_D;
        float a0 = 0.f, a1 = 0.f, a2 = 0.f, a3 = 0.f;
        #pragma unroll
        for (int j = 0; j < VQ_D; j += 4) {
            a0 = fmaf(e[j+0], e[j+0], a0);
            a1 = fmaf(e[j+1], e[j+1], a1);
            a2 = fmaf(e[j+2], e[j+2], a2);
            a3 = fmaf(e[j+3], e[j+3], a3);
        }
        sh_ee[kk] = __fadd_rn(__fadd_rn(a0, a1), __fadd_rn(a2, a3));
    }
    __syncthreads();

    const int row = blockIdx.x * BLOCK_THREADS + tid;
    float s_loss = 0.f;

    if (row < n) {
        // --- x row into registers as 32 packed f32x2 values ---
        u64 xr[VQ_D / 2];
        {
            const ulonglong2* xp = (const ulonglong2*)(x + (size_t)row * VQ_D);
            #pragma unroll
            for (int j = 0; j < VQ_D / 4; j++) {
                ulonglong2 v = xp[j];
                xr[2*j]   = v.x;
                xr[2*j+1] = v.y;
            }
        }

        // --- ||x||^2 ---
        float xx;
        {
            float a0 = 0.f, a1 = 0.f, a2 = 0.f, a3 = 0.f;
            #pragma unroll
            for (int j = 0; j < VQ_D / 2; j += 2) {
                float2 fa = u2f(xr[j]), fb = u2f(xr[j+1]);
                a0 = fmaf(fa.x, fa.x, a0);
                a1 = fmaf(fa.y, fa.y, a1);
                a2 = fmaf(fb.x, fb.x, a2);
                a3 = fmaf(fb.y, fb.y, a3);
            }
            xx = __fadd_rn(__fadd_rn(a0, a1), __fadd_rn(a2, a3));
        }

        // --- argmin over K codes ---
        float best = 3.402823466e38f;
        int   bi   = 0;
        const ulonglong2* ebase = (const ulonglong2*)sh_cb;

        #pragma unroll 2
        for (int kk = 0; kk < K; kk++) {
            const ulonglong2* e = ebase + (size_t)kk * (VQ_D / 4);
            u64 a0 = 0ull, a1 = 0ull, a2 = 0ull, a3 = 0ull;
            #pragma unroll
            for (int j = 0; j < VQ_D / 4; j += 2) {
                ulonglong2 e0 = e[j];
                ulonglong2 e1 = e[j + 1];
                a0 = fma2(e0.x, xr[2*j    ], a0);
                a1 = fma2(e0.y, xr[2*j + 1], a1);
                a2 = fma2(e1.x, xr[2*j + 2], a2);
                a3 = fma2(e1.y, xr[2*j + 3], a3);
            }
            u64 s = add2(add2(a0, a1), add2(a2, a3));
            float2 sf = u2f(s);
            float dot  = __fadd_rn(sf.x, sf.y);
            // (xx + ee) first, then subtract 2*dot WITHOUT fma contraction
            float dist = __fadd_rn(__fadd_rn(xx, sh_ee[kk]),
                                   -__fmul_rn(2.0f, dot));
            if (dist < best) { best = dist; bi = kk; }
        }

        // --- outputs: index (as float), quantized row, loss partial ---
        out[row] = (float)bi;

        const float*  e  = sh_cb + (size_t)bi * VQ_D;
        const float4* e4 = (const float4*)e;
        float4* q4 = (float4*)(out + (size_t)n + (size_t)row * VQ_D);
        #pragma unroll
        for (int j = 0; j < VQ_D / 4; j++) q4[j] = e4[j];

        float l0 = 0.f, l1 = 0.f, l2 = 0.f, l3 = 0.f;
        #pragma unroll
        for (int j2 = 0; j2 < VQ_D / 2; j2 += 2) {
            float2 fa = u2f(xr[j2]), fb = u2f(xr[j2 + 1]);
            float d0 = e[2*j2 + 0] - fa.x;
            float d1 = e[2*j2 + 1] - fa.y;
            float d2 = e[2*j2 + 2] - fb.x;
            float d3 = e[2*j2 + 3] - fb.y;
            l0 = fmaf(d0, d0, l0);
            l1 = fmaf(d1, d1, l1);
            l2 = fmaf(d2, d2, l2);
            l3 = fmaf(d3, d3, l3);
        }
        s_loss = __fadd_rn(__fadd_rn(l0, l1), __fadd_rn(l2, l3));
    }

    // --- deterministic block reduce of s_loss ---
    #pragma unroll
    for (int off = 16; off > 0; off >>= 1)
        s_loss += __shfl_down_sync(0xffffffffu, s_loss, off);
    if ((tid & 31) == 0) sh_red[tid >> 5] = s_loss;
    __syncthreads();
    if (tid == 0) {
        float t = 0.f;
        #pragma unroll
        for (int w = 0; w < BLOCK_THREADS / 32; w++) t += sh_red[w];
        g_vq_partials[blockIdx.x] = t;
    }
}

// ---------------------------------------------------------------------------
// Final deterministic reduction -> vq_loss = 1.25 * mean((q - x)^2)
// ---------------------------------------------------------------------------
__global__ void vq_reduce_kernel(float* __restrict__ out, int n, int nblocks)
{
    __shared__ double shd[BLOCK_THREADS];
    double s = 0.0;
    for (int i = threadIdx.x; i < nblocks; i += BLOCK_THREADS)
        s += (double)g_vq_partials[i];
    shd[threadIdx.x] = s;
    __syncthreads();
    for (int off = BLOCK_THREADS / 2; off > 0; off >>= 1) {
        if (threadIdx.x < off) shd[threadIdx.x] += shd[threadIdx.x + off];
        __syncthreads();
    }
    if (threadIdx.x == 0) {
        double mean = shd[0] / ((double)n * (double)VQ_D);
        out[(size_t)n + (size_t)n * VQ_D] = (float)(mean * 1.25);
    }
}

extern "C" void kernel_launch(void* const* d_in, const int* in_sizes, int n_in,
                              void* d_out, int out_size)
{
    const float* x  = (const float*)d_in[0];
    const float* cb = (const float*)d_in[1];
    float* out = (float*)d_out;

    const int n = in_sizes[0] / VQ_D;   // 524288
    const int K = in_sizes[1] / VQ_D;   // 512

    const int nblocks = (n + BLOCK_THREADS - 1) / BLOCK_THREADS;  // 2048
    const size_t smem = (size_t)K * VQ_D * sizeof(float)          // codebook
                      + (size_t)K * sizeof(float)                 // norms
                      + 64 * sizeof(float);                       // reduce pad

    cudaFuncSetAttribute(vq_main_kernel,
                         cudaFuncAttributeMaxDynamicSharedMemorySize,
                         (int)smem);

    vq_main_kernel<<<nblocks, BLOCK_THREADS, smem>>>(x, cb, out, n, K);
    vq_reduce_kernel<<<1, BLOCK_THREADS>>>(out, n, nblocks);
}